// round 12
// baseline (speedup 1.0000x reference)
#include <cuda_runtime.h>
#include <cuda_bf16.h>
#include <cuda_fp16.h>
#include <stdint.h>
#include <math.h>

// Problem constants
#define TSTEPS 512
#define B_ 256
#define H_ 1024
#define K_ 1024
#define BH_ (B_ * H_)

// Scan SMEM: Wh resident fp16, 16 chunks x 4KB (32n x 64k each)
#define OFF_WH   0
#define SMEM_TOTAL 65536

// h in mma-A-fragment layout:
// [parity][mtile(4)][rowgrp(4)][kstep(64)][lane(32)] x uint4  = 2MB total
__device__ uint4 g_frag[2][4][4][64][32];
// per-producer-warp step slots: [mtile][rowgrp][kstep] -> last completed step+1
__device__ unsigned g_slot[4][4][64];
// scan-finish counter (for in-kernel slot reset)
__device__ unsigned g_finish;

// ---------------------------------------------------------------------------
// Helpers
// ---------------------------------------------------------------------------
__device__ __forceinline__ uint32_t smem_u32(const void* p) {
    uint32_t a;
    asm("{ .reg .u64 t; cvta.to.shared.u64 t, %1; cvt.u32.u64 %0, t; }"
        : "=r"(a) : "l"(p));
    return a;
}
__device__ __forceinline__ uint32_t sw128(uint32_t off) {
    return off ^ ((off >> 3) & 0x70);
}
__device__ __forceinline__ void ldsm4(uint32_t r[4], uint32_t addr) {
    asm volatile("ldmatrix.sync.aligned.m8n8.x4.shared.b16 {%0,%1,%2,%3}, [%4];"
                 : "=r"(r[0]), "=r"(r[1]), "=r"(r[2]), "=r"(r[3]) : "r"(addr));
}
__device__ __forceinline__ void mma_bf16(float c[4], const uint32_t a[4],
                                         uint32_t b0, uint32_t b1) {
    asm volatile(
        "mma.sync.aligned.m16n8k16.row.col.f32.bf16.bf16.f32 "
        "{%0,%1,%2,%3}, {%4,%5,%6,%7}, {%8,%9}, {%0,%1,%2,%3};"
        : "+f"(c[0]), "+f"(c[1]), "+f"(c[2]), "+f"(c[3])
        : "r"(a[0]), "r"(a[1]), "r"(a[2]), "r"(a[3]), "r"(b0), "r"(b1));
}
__device__ __forceinline__ void mma_f16(float c[4], const uint32_t a[4],
                                        uint32_t b0, uint32_t b1) {
    asm volatile(
        "mma.sync.aligned.m16n8k16.row.col.f32.f16.f16.f32 "
        "{%0,%1,%2,%3}, {%4,%5,%6,%7}, {%8,%9}, {%0,%1,%2,%3};"
        : "+f"(c[0]), "+f"(c[1]), "+f"(c[2]), "+f"(c[3])
        : "r"(a[0]), "r"(a[1]), "r"(a[2]), "r"(a[3]), "r"(b0), "r"(b1));
}
__device__ __forceinline__ uint32_t pack2bf(__nv_bfloat16 a, __nv_bfloat16 b) {
    return ((uint32_t)__bfloat16_as_ushort(b) << 16) | __bfloat16_as_ushort(a);
}
__device__ __forceinline__ uint32_t pack2h(__half a, __half b) {
    return ((uint32_t)__half_as_ushort(b) << 16) | __half_as_ushort(a);
}
__device__ __forceinline__ void split_store_bf(float4 v, char* hiBase, char* loBase,
                                               uint32_t off) {
    __nv_bfloat16 h0 = __float2bfloat16(v.x);
    __nv_bfloat16 h1 = __float2bfloat16(v.y);
    __nv_bfloat16 h2 = __float2bfloat16(v.z);
    __nv_bfloat16 h3 = __float2bfloat16(v.w);
    float l0 = v.x - __bfloat162float(h0);
    float l1 = v.y - __bfloat162float(h1);
    float l2 = v.z - __bfloat162float(h2);
    float l3 = v.w - __bfloat162float(h3);
    uint32_t s = sw128(off);
    *(uint2*)(hiBase + s) = make_uint2(pack2bf(h0, h1), pack2bf(h2, h3));
    *(uint2*)(loBase + s) = make_uint2(pack2bf(__float2bfloat16(l0), __float2bfloat16(l1)),
                                       pack2bf(__float2bfloat16(l2), __float2bfloat16(l3)));
}
__device__ __forceinline__ void round_store_h(float4 v, char* base, uint32_t off) {
    uint32_t s = sw128(off);
    *(uint2*)(base + s) = make_uint2(
        pack2h(__float2half(v.x), __float2half(v.y)),
        pack2h(__float2half(v.z), __float2half(v.w)));
}
__device__ __forceinline__ uint4 ldgcg4(const uint4* p) {
    uint4 v;
    asm volatile("ld.global.cg.v4.u32 {%0,%1,%2,%3}, [%4];"
                 : "=r"(v.x), "=r"(v.y), "=r"(v.z), "=r"(v.w) : "l"(p));
    return v;
}
__device__ __forceinline__ void stg4(uint4* p, uint4 v) {
    asm volatile("st.global.v4.u32 [%0], {%1,%2,%3,%4};"
                 :: "l"(p), "r"(v.x), "r"(v.y), "r"(v.z), "r"(v.w) : "memory");
}

// ---------------------------------------------------------------------------
// Phase 1: xp[m,n] = x[m,:] . Wx[n,:] + bx[n]   (3-term bf16 HMMA; unchanged)
// ---------------------------------------------------------------------------
__global__ void __launch_bounds__(256, 1) gemm_xp_kernel(
    const float* __restrict__ A, const float* __restrict__ W,
    const float* __restrict__ bias, float* __restrict__ C)
{
    __shared__ __align__(1024) char sAh[128 * 128];
    __shared__ __align__(1024) char sAl[128 * 128];
    __shared__ __align__(1024) char sBh[64 * 128];
    __shared__ __align__(1024) char sBl[64 * 128];

    const int tid = threadIdx.x;
    const int wid = tid >> 5, lane = tid & 31;
    const int m0 = blockIdx.y * 128;
    const int n0 = blockIdx.x * 64;
    const int wm = (wid >> 1) * 32;
    const int wn = (wid & 1) * 32;

    const uint32_t uAh = smem_u32(sAh), uAl = smem_u32(sAl);
    const uint32_t uBh = smem_u32(sBh), uBl = smem_u32(sBl);

    const int ar = tid >> 4;
    const int ac = tid & 15;
    const float4* __restrict__ A4 = (const float4*)A;
    const float4* __restrict__ W4 = (const float4*)W;

    float c[2][4][4] = {};
    float4 pa[8], pb[4];

    #pragma unroll
    for (int p = 0; p < 8; p++)
        pa[p] = A4[(size_t)(m0 + ar + p * 16) * 256 + ac];
    #pragma unroll
    for (int p = 0; p < 4; p++)
        pb[p] = W4[(size_t)(n0 + ar + p * 16) * 256 + ac];

    for (int ch = 0; ch < 16; ch++) {
        if (ch > 0) __syncthreads();
        #pragma unroll
        for (int p = 0; p < 8; p++)
            split_store_bf(pa[p], sAh, sAl, (uint32_t)((ar + p * 16) * 128 + ac * 8));
        #pragma unroll
        for (int p = 0; p < 4; p++)
            split_store_bf(pb[p], sBh, sBl, (uint32_t)((ar + p * 16) * 128 + ac * 8));
        __syncthreads();

        if (ch < 15) {
            const int kc = (ch + 1) * 16;
            #pragma unroll
            for (int p = 0; p < 8; p++)
                pa[p] = A4[(size_t)(m0 + ar + p * 16) * 256 + kc + ac];
            #pragma unroll
            for (int p = 0; p < 4; p++)
                pb[p] = W4[(size_t)(n0 + ar + p * 16) * 256 + kc + ac];
        }

        #pragma unroll
        for (int ks = 0; ks < 4; ks++) {
            const int q = lane >> 3;
            uint32_t ah[2][4], al[2][4];
            #pragma unroll
            for (int mi = 0; mi < 2; mi++) {
                uint32_t r = (uint32_t)(wm + mi * 16 + (lane & 7) + (q & 1) * 8);
                uint32_t kb = (uint32_t)(ks * 32 + (q >> 1) * 16);
                uint32_t so = sw128(r * 128 + kb);
                ldsm4(ah[mi], uAh + so);
                ldsm4(al[mi], uAl + so);
            }
            uint32_t bhf[2][4], blf[2][4];
            #pragma unroll
            for (int g = 0; g < 2; g++) {
                uint32_t rn = (uint32_t)(wn + g * 16 + (lane & 7) + (q >> 1) * 8);
                uint32_t kb = (uint32_t)(ks * 32 + (q & 1) * 16);
                uint32_t so = sw128(rn * 128 + kb);
                ldsm4(bhf[g], uBh + so);
                ldsm4(blf[g], uBl + so);
            }
            #pragma unroll
            for (int mi = 0; mi < 2; mi++)
                #pragma unroll
                for (int ni = 0; ni < 4; ni++) {
                    uint32_t b0h = bhf[ni >> 1][(ni & 1) * 2];
                    uint32_t b1h = bhf[ni >> 1][(ni & 1) * 2 + 1];
                    uint32_t b0l = blf[ni >> 1][(ni & 1) * 2];
                    uint32_t b1l = blf[ni >> 1][(ni & 1) * 2 + 1];
                    mma_bf16(c[mi][ni], ah[mi], b0h, b1h);
                    mma_bf16(c[mi][ni], ah[mi], b0l, b1l);
                    mma_bf16(c[mi][ni], al[mi], b0h, b1h);
                }
        }
    }

    const int t4 = lane >> 2, cp = (lane & 3) * 2;
    #pragma unroll
    for (int mi = 0; mi < 2; mi++) {
        #pragma unroll
        for (int ni = 0; ni < 4; ni++) {
            const int col = n0 + wn + ni * 8 + cp;
            float2 bv = *(const float2*)&bias[col];
            const int r0 = m0 + wm + mi * 16 + t4;
            float2 v0 = make_float2(c[mi][ni][0] + bv.x, c[mi][ni][1] + bv.y);
            float2 v1 = make_float2(c[mi][ni][2] + bv.x, c[mi][ni][3] + bv.y);
            *(float2*)&C[(size_t)r0 * H_ + col] = v0;
            *(float2*)&C[(size_t)(r0 + 8) * H_ + col] = v1;
        }
    }
}

// ---------------------------------------------------------------------------
// Phase 2: persistent scan. R11 compute core + store-flag dataflow sync.
// Grid (32, 4) = 128 CTAs, 256 threads; 8 warps (4 rowgrps x 2 n), warp tile
// 16m x 16n, depth-2 stage pipeline. Sync: per-producer-warp slot words
// g_slot[by][rowgrp][kstep] = completed step + 1 (st.release by lane0 after
// the warp's frag store). Consumers poll the 16 slots of a stage with
// relaxed loads + ballot, then fence.acq_rel. Exact dataflow granularity:
// consumer warp of rowgrp rg depends only on producer warps of rowgrp rg.
// fp32 hall/hfinal stores happen AFTER the release (off the critical path).
// ---------------------------------------------------------------------------
__global__ void __launch_bounds__(256, 1) rnn_scan_kernel(
    const float* __restrict__ Wh, const float* __restrict__ bh,
    float* __restrict__ hall, float* __restrict__ hfinal)
{
    extern __shared__ __align__(1024) char smem[];

    const int tid = threadIdx.x;
    const int wid = tid >> 5, lane = tid & 31;
    const int bx = blockIdx.x;           // n-tile 0..31
    const int by = blockIdx.y;           // m-tile 0..3
    const int n0 = bx * 32;
    const int m0 = by * 64;

    const uint32_t uWh = smem_u32(smem + OFF_WH);

    // ---- one-time: round Wh tile to fp16 into resident SMEM ----
    {
        const float4* __restrict__ W4 = (const float4*)Wh;
        for (int i = tid; i < 8192; i += 256) {
            int r  = i >> 8;          // n row 0..31
            int f4 = i & 255;         // float4 col
            int c  = f4 >> 4;         // chunk 0..15
            int fc = f4 & 15;
            float4 v = W4[(size_t)(n0 + r) * 256 + f4];
            round_store_h(v, smem + OFF_WH + c * 4096,
                          (uint32_t)(r * 128 + fc * 8));
        }
    }
    __syncthreads();

    // warp mapping: 8 warps = 4m-rowgrps x 2n; warp tile 16(m) x 16(n)
    const int rowgrp = wid >> 1;
    const int wm = rowgrp * 16;
    const int wn = (wid & 1) * 16;
    const int t4 = lane >> 2, cp = (lane & 3) * 2;
    const int q = lane >> 3;
    float2 bv[2];
    bv[0] = *(const float2*)&bh[n0 + wn + 0 + cp];
    bv[1] = *(const float2*)&bh[n0 + wn + 8 + cp];

    // B ldsm base offsets per ksl (0..3), chunk-relative (swizzled)
    uint32_t boff[4];
    {
        uint32_t rn = (uint32_t)(wn + (lane & 7) + (q >> 1) * 8);
        #pragma unroll
        for (int ksl = 0; ksl < 4; ksl++)
            boff[ksl] = sw128(rn * 128 + (uint32_t)(ksl * 32 + (q & 1) * 16));
    }

    const int kstep_w = bx * 2 + (wn >> 4);
    unsigned* const slotbase = &g_slot[by][rowgrp][0];
    unsigned* const myslot   = &g_slot[by][rowgrp][kstep_w];

    // wait for the 16 producer-warp slots of stage S to reach TGT
    #define WAITFLAG(S, TGT)                                                  \
        do {                                                                  \
            const unsigned* sp = &slotbase[(S) * 16 + (lane & 15)];           \
            while (1) {                                                       \
                unsigned val;                                                 \
                asm volatile("ld.relaxed.gpu.global.u32 %0, [%1];"            \
                             : "=r"(val) : "l"(sp));                          \
                unsigned msk = __ballot_sync(0xFFFFFFFFu, val >= (TGT));      \
                if (msk == 0xFFFFFFFFu) break;                                \
            }                                                                 \
            asm volatile("fence.acq_rel.gpu;" ::: "memory");                  \
        } while (0)

    #define LOADSTAGE(DST, S)                                                 \
        do {                                                                  \
            _Pragma("unroll")                                                 \
            for (int i = 0; i < 16; i++)                                      \
                DST[i] = ldgcg4(fbase + ((S) * 16 + i) * 32);                 \
        } while (0)

    #define COMPSTAGE(SRC, S)                                                 \
        do {                                                                  \
            _Pragma("unroll")                                                 \
            for (int i = 0; i < 16; i++) {                                    \
                const int ks = (S) * 16 + i;                                  \
                const int ch = ks >> 2, ksl = ks & 3;                         \
                uint32_t bf[4];                                               \
                ldsm4(bf, uWh + ch * 4096 + boff[ksl]);                       \
                if (i & 1) {                                                  \
                    mma_f16(c1[0], (const uint32_t*)&SRC[i], bf[0], bf[1]);   \
                    mma_f16(c1[1], (const uint32_t*)&SRC[i], bf[2], bf[3]);   \
                } else {                                                      \
                    mma_f16(c0[0], (const uint32_t*)&SRC[i], bf[0], bf[1]);   \
                    mma_f16(c0[1], (const uint32_t*)&SRC[i], bf[2], bf[3]);   \
                }                                                             \
            }                                                                 \
        } while (0)

    for (int t = 0; t < TSTEPS; t++) {
        float c0[2][4] = {}, c1[2][4] = {};
        float* __restrict__ xp = hall + (size_t)t * BH_;

        // prefetch xp for epilogue
        float2 xv[2][2];
        #pragma unroll
        for (int ni = 0; ni < 2; ni++)
            #pragma unroll
            for (int h = 0; h < 2; h++) {
                const int r = m0 + wm + t4 + h * 8;
                const int col = n0 + wn + ni * 8 + cp;
                xv[ni][h] = *(const float2*)&xp[(size_t)r * H_ + col];
            }

        if (t > 0) {
            const uint4* __restrict__ fbase =
                &g_frag[(t - 1) & 1][by][rowgrp][0][lane];
            const unsigned tgt = (unsigned)t;   // slot >= t means step t-1 done

            uint4 a0[16], a1[16];
            WAITFLAG(0, tgt);
            LOADSTAGE(a0, 0);

            WAITFLAG(1, tgt);
            LOADSTAGE(a1, 1);
            COMPSTAGE(a0, 0);

            WAITFLAG(2, tgt);
            LOADSTAGE(a0, 2);
            COMPSTAGE(a1, 1);

            WAITFLAG(3, tgt);
            LOADSTAGE(a1, 3);
            COMPSTAGE(a0, 2);

            COMPSTAGE(a1, 3);

            #pragma unroll
            for (int ni = 0; ni < 2; ni++)
                #pragma unroll
                for (int r = 0; r < 4; r++)
                    c0[ni][r] += c1[ni][r];
        }

        // ---- epilogue: tanh -> frag store -> RELEASE -> fp32 stores ----
        {
            float v[2][2][2];   // [ni][h][pair]
            #pragma unroll
            for (int ni = 0; ni < 2; ni++)
                #pragma unroll
                for (int h = 0; h < 2; h++) {
                    float v0 = tanhf(c0[ni][h * 2]     + xv[ni][h].x + bv[ni].x);
                    float v1 = tanhf(c0[ni][h * 2 + 1] + xv[ni][h].y + bv[ni].y);
                    v[ni][h][0] = v0; v[ni][h][1] = v1;
                }

            // fragment store + release FIRST (critical path for consumers)
            uint4 fv;
            fv.x = pack2h(__float2half(v[0][0][0]), __float2half(v[0][0][1]));
            fv.y = pack2h(__float2half(v[0][1][0]), __float2half(v[0][1][1]));
            fv.z = pack2h(__float2half(v[1][0][0]), __float2half(v[1][0][1]));
            fv.w = pack2h(__float2half(v[1][1][0]), __float2half(v[1][1][1]));
            stg4(&g_frag[t & 1][by][rowgrp][kstep_w][lane], fv);
            if (t < TSTEPS - 1) {
                __syncwarp();
                if (lane == 0)
                    asm volatile("st.release.gpu.global.u32 [%0], %1;"
                                 :: "l"(myslot), "r"((unsigned)(t + 1))
                                 : "memory");
            }

            // fp32 outputs (off the inter-CTA critical path)
            #pragma unroll
            for (int ni = 0; ni < 2; ni++) {
                const int col = n0 + wn + ni * 8 + cp;
                #pragma unroll
                for (int h = 0; h < 2; h++) {
                    const int r = m0 + wm + t4 + h * 8;
                    *(float2*)&xp[(size_t)r * H_ + col] =
                        make_float2(v[ni][h][0], v[ni][h][1]);
                    if (t == TSTEPS - 1)
                        *(float2*)&hfinal[(size_t)r * H_ + col] =
                            make_float2(v[ni][h][0], v[ni][h][1]);
                }
            }
        }
    }

    // ---- in-kernel slot reset: last-finishing CTA zeroes all slots ----
    __syncthreads();
    if (tid == 0) {
        unsigned prev;
        asm volatile("atom.add.release.gpu.u32 %0, [%1], 1;"
                     : "=r"(prev) : "l"(&g_finish));
        if (prev == 127u) {
            unsigned* sl = &g_slot[0][0][0];
            for (int i = 0; i < 4 * 4 * 64; i += 4)
                asm volatile("st.relaxed.gpu.global.v4.u32 [%0], {%1,%1,%1,%1};"
                             :: "l"(&sl[i]), "r"(0u) : "memory");
            asm volatile("st.relaxed.gpu.u32 [%0], %1;"
                         :: "l"(&g_finish), "r"(0u));
        }
    }

    #undef WAITFLAG
    #undef LOADSTAGE
    #undef COMPSTAGE
}

// ---------------------------------------------------------------------------
// kernel_launch: gemm_xp, then persistent scan (slots self-reset).
// ---------------------------------------------------------------------------
extern "C" void kernel_launch(void* const* d_in, const int* in_sizes, int n_in,
                              void* d_out, int out_size)
{
    const float* x  = (const float*)d_in[0];
    const float* Wx = (const float*)d_in[1];
    const float* bx = (const float*)d_in[2];
    const float* Wh = (const float*)d_in[3];
    const float* bh = (const float*)d_in[4];

    float* out    = (float*)d_out;
    float* hfinal = out;                 // [B_ * H_]
    float* hall   = out + BH_;           // [TSTEPS * B_ * H_]

    static int smem_set = 0;
    if (!smem_set) {
        cudaFuncSetAttribute(rnn_scan_kernel,
                             cudaFuncAttributeMaxDynamicSharedMemorySize,
                             SMEM_TOTAL);
        smem_set = 1;
    }

    // Phase 1: xp for all timesteps
    gemm_xp_kernel<<<dim3(16, 1024), 256>>>(x, Wx, bx, hall);

    // Phase 2: persistent tensor-core scan (128 CTAs, all resident)
    rnn_scan_kernel<<<dim3(32, 4), 256, SMEM_TOTAL>>>(Wh, bh, hall, hfinal);
}

// round 13
// speedup vs baseline: 1.5289x; 1.5289x over previous
#include <cuda_runtime.h>
#include <cuda_bf16.h>
#include <cuda_fp16.h>
#include <stdint.h>
#include <math.h>

// Problem constants
#define TSTEPS 512
#define B_ 256
#define H_ 1024
#define K_ 1024
#define BH_ (B_ * H_)

// Scan SMEM: Wh resident fp16, 16 chunks x 4KB (32n x 64k each)
#define OFF_WH   0
#define SMEM_TOTAL 65536

// h in mma-A-fragment layout:
// [parity][mtile(4)][rowgrp(4)][kstep(64)][lane(32)] x uint4  = 2MB total
__device__ uint4 g_frag[2][4][4][64][32];
// per-(mtile, stage) monotonic warp-arrival flags (padded to 128B lines)
__device__ unsigned g_done[4 * 4 * 32];
// scan-finish counter (for in-kernel flag reset)
__device__ unsigned g_finish;

// ---------------------------------------------------------------------------
// Helpers
// ---------------------------------------------------------------------------
__device__ __forceinline__ uint32_t smem_u32(const void* p) {
    uint32_t a;
    asm("{ .reg .u64 t; cvta.to.shared.u64 t, %1; cvt.u32.u64 %0, t; }"
        : "=r"(a) : "l"(p));
    return a;
}
__device__ __forceinline__ uint32_t sw128(uint32_t off) {
    return off ^ ((off >> 3) & 0x70);
}
__device__ __forceinline__ void ldsm4(uint32_t r[4], uint32_t addr) {
    asm volatile("ldmatrix.sync.aligned.m8n8.x4.shared.b16 {%0,%1,%2,%3}, [%4];"
                 : "=r"(r[0]), "=r"(r[1]), "=r"(r[2]), "=r"(r[3]) : "r"(addr));
}
__device__ __forceinline__ void mma_bf16(float c[4], const uint32_t a[4],
                                         uint32_t b0, uint32_t b1) {
    asm volatile(
        "mma.sync.aligned.m16n8k16.row.col.f32.bf16.bf16.f32 "
        "{%0,%1,%2,%3}, {%4,%5,%6,%7}, {%8,%9}, {%0,%1,%2,%3};"
        : "+f"(c[0]), "+f"(c[1]), "+f"(c[2]), "+f"(c[3])
        : "r"(a[0]), "r"(a[1]), "r"(a[2]), "r"(a[3]), "r"(b0), "r"(b1));
}
__device__ __forceinline__ void mma_f16(float c[4], const uint32_t a[4],
                                        uint32_t b0, uint32_t b1) {
    asm volatile(
        "mma.sync.aligned.m16n8k16.row.col.f32.f16.f16.f32 "
        "{%0,%1,%2,%3}, {%4,%5,%6,%7}, {%8,%9}, {%0,%1,%2,%3};"
        : "+f"(c[0]), "+f"(c[1]), "+f"(c[2]), "+f"(c[3])
        : "r"(a[0]), "r"(a[1]), "r"(a[2]), "r"(a[3]), "r"(b0), "r"(b1));
}
__device__ __forceinline__ uint32_t pack2bf(__nv_bfloat16 a, __nv_bfloat16 b) {
    return ((uint32_t)__bfloat16_as_ushort(b) << 16) | __bfloat16_as_ushort(a);
}
__device__ __forceinline__ uint32_t pack2h(__half a, __half b) {
    return ((uint32_t)__half_as_ushort(b) << 16) | __half_as_ushort(a);
}
__device__ __forceinline__ void split_store_bf(float4 v, char* hiBase, char* loBase,
                                               uint32_t off) {
    __nv_bfloat16 h0 = __float2bfloat16(v.x);
    __nv_bfloat16 h1 = __float2bfloat16(v.y);
    __nv_bfloat16 h2 = __float2bfloat16(v.z);
    __nv_bfloat16 h3 = __float2bfloat16(v.w);
    float l0 = v.x - __bfloat162float(h0);
    float l1 = v.y - __bfloat162float(h1);
    float l2 = v.z - __bfloat162float(h2);
    float l3 = v.w - __bfloat162float(h3);
    uint32_t s = sw128(off);
    *(uint2*)(hiBase + s) = make_uint2(pack2bf(h0, h1), pack2bf(h2, h3));
    *(uint2*)(loBase + s) = make_uint2(pack2bf(__float2bfloat16(l0), __float2bfloat16(l1)),
                                       pack2bf(__float2bfloat16(l2), __float2bfloat16(l3)));
}
__device__ __forceinline__ void round_store_h(float4 v, char* base, uint32_t off) {
    uint32_t s = sw128(off);
    *(uint2*)(base + s) = make_uint2(
        pack2h(__float2half(v.x), __float2half(v.y)),
        pack2h(__float2half(v.z), __float2half(v.w)));
}
__device__ __forceinline__ uint4 ldgcg4(const uint4* p) {
    uint4 v;
    asm volatile("ld.global.cg.v4.u32 {%0,%1,%2,%3}, [%4];"
                 : "=r"(v.x), "=r"(v.y), "=r"(v.z), "=r"(v.w) : "l"(p));
    return v;
}
__device__ __forceinline__ void stg4(uint4* p, uint4 v) {
    asm volatile("st.global.v4.u32 [%0], {%1,%2,%3,%4};"
                 :: "l"(p), "r"(v.x), "r"(v.y), "r"(v.z), "r"(v.w) : "memory");
}

// ---------------------------------------------------------------------------
// Phase 1: xp[m,n] = x[m,:] . Wx[n,:] + bx[n]   (3-term bf16 HMMA; unchanged)
// ---------------------------------------------------------------------------
__global__ void __launch_bounds__(256, 1) gemm_xp_kernel(
    const float* __restrict__ A, const float* __restrict__ W,
    const float* __restrict__ bias, float* __restrict__ C)
{
    __shared__ __align__(1024) char sAh[128 * 128];
    __shared__ __align__(1024) char sAl[128 * 128];
    __shared__ __align__(1024) char sBh[64 * 128];
    __shared__ __align__(1024) char sBl[64 * 128];

    const int tid = threadIdx.x;
    const int wid = tid >> 5, lane = tid & 31;
    const int m0 = blockIdx.y * 128;
    const int n0 = blockIdx.x * 64;
    const int wm = (wid >> 1) * 32;
    const int wn = (wid & 1) * 32;

    const uint32_t uAh = smem_u32(sAh), uAl = smem_u32(sAl);
    const uint32_t uBh = smem_u32(sBh), uBl = smem_u32(sBl);

    const int ar = tid >> 4;
    const int ac = tid & 15;
    const float4* __restrict__ A4 = (const float4*)A;
    const float4* __restrict__ W4 = (const float4*)W;

    float c[2][4][4] = {};
    float4 pa[8], pb[4];

    #pragma unroll
    for (int p = 0; p < 8; p++)
        pa[p] = A4[(size_t)(m0 + ar + p * 16) * 256 + ac];
    #pragma unroll
    for (int p = 0; p < 4; p++)
        pb[p] = W4[(size_t)(n0 + ar + p * 16) * 256 + ac];

    for (int ch = 0; ch < 16; ch++) {
        if (ch > 0) __syncthreads();
        #pragma unroll
        for (int p = 0; p < 8; p++)
            split_store_bf(pa[p], sAh, sAl, (uint32_t)((ar + p * 16) * 128 + ac * 8));
        #pragma unroll
        for (int p = 0; p < 4; p++)
            split_store_bf(pb[p], sBh, sBl, (uint32_t)((ar + p * 16) * 128 + ac * 8));
        __syncthreads();

        if (ch < 15) {
            const int kc = (ch + 1) * 16;
            #pragma unroll
            for (int p = 0; p < 8; p++)
                pa[p] = A4[(size_t)(m0 + ar + p * 16) * 256 + kc + ac];
            #pragma unroll
            for (int p = 0; p < 4; p++)
                pb[p] = W4[(size_t)(n0 + ar + p * 16) * 256 + kc + ac];
        }

        #pragma unroll
        for (int ks = 0; ks < 4; ks++) {
            const int q = lane >> 3;
            uint32_t ah[2][4], al[2][4];
            #pragma unroll
            for (int mi = 0; mi < 2; mi++) {
                uint32_t r = (uint32_t)(wm + mi * 16 + (lane & 7) + (q & 1) * 8);
                uint32_t kb = (uint32_t)(ks * 32 + (q >> 1) * 16);
                uint32_t so = sw128(r * 128 + kb);
                ldsm4(ah[mi], uAh + so);
                ldsm4(al[mi], uAl + so);
            }
            uint32_t bhf[2][4], blf[2][4];
            #pragma unroll
            for (int g = 0; g < 2; g++) {
                uint32_t rn = (uint32_t)(wn + g * 16 + (lane & 7) + (q >> 1) * 8);
                uint32_t kb = (uint32_t)(ks * 32 + (q & 1) * 16);
                uint32_t so = sw128(rn * 128 + kb);
                ldsm4(bhf[g], uBh + so);
                ldsm4(blf[g], uBl + so);
            }
            #pragma unroll
            for (int mi = 0; mi < 2; mi++)
                #pragma unroll
                for (int ni = 0; ni < 4; ni++) {
                    uint32_t b0h = bhf[ni >> 1][(ni & 1) * 2];
                    uint32_t b1h = bhf[ni >> 1][(ni & 1) * 2 + 1];
                    uint32_t b0l = blf[ni >> 1][(ni & 1) * 2];
                    uint32_t b1l = blf[ni >> 1][(ni & 1) * 2 + 1];
                    mma_bf16(c[mi][ni], ah[mi], b0h, b1h);
                    mma_bf16(c[mi][ni], ah[mi], b0l, b1l);
                    mma_bf16(c[mi][ni], al[mi], b0h, b1h);
                }
        }
    }

    const int t4 = lane >> 2, cp = (lane & 3) * 2;
    #pragma unroll
    for (int mi = 0; mi < 2; mi++) {
        #pragma unroll
        for (int ni = 0; ni < 4; ni++) {
            const int col = n0 + wn + ni * 8 + cp;
            float2 bv = *(const float2*)&bias[col];
            const int r0 = m0 + wm + mi * 16 + t4;
            float2 v0 = make_float2(c[mi][ni][0] + bv.x, c[mi][ni][1] + bv.y);
            float2 v1 = make_float2(c[mi][ni][2] + bv.x, c[mi][ni][3] + bv.y);
            *(float2*)&C[(size_t)r0 * H_ + col] = v0;
            *(float2*)&C[(size_t)(r0 + 8) * H_ + col] = v1;
        }
    }
}

// ---------------------------------------------------------------------------
// Phase 2: persistent scan (R11 config: atomic-counter flags + depth-2
// pipeline) with reordered epilogue: frag store + release happen BEFORE the
// fp32 output stores, shortening the producer->consumer handoff.
// Grid (32, 4) = 128 CTAs, 256 threads; 8 warps (4 rowgrps x 2 n), warp tile
// 16m x 16n. Flags: stage s produced by CTAs bx in [8s,8s+8) => 64 warp-
// arrivals/step; lane0 acquire-poll (spin 32, then nanosleep backoff).
// ---------------------------------------------------------------------------
__global__ void __launch_bounds__(256, 1) rnn_scan_kernel(
    const float* __restrict__ Wh, const float* __restrict__ bh,
    float* __restrict__ hall, float* __restrict__ hfinal)
{
    extern __shared__ __align__(1024) char smem[];

    const int tid = threadIdx.x;
    const int wid = tid >> 5, lane = tid & 31;
    const int bx = blockIdx.x;           // n-tile 0..31
    const int by = blockIdx.y;           // m-tile 0..3
    const int n0 = bx * 32;
    const int m0 = by * 64;

    const uint32_t uWh = smem_u32(smem + OFF_WH);

    // ---- one-time: round Wh tile to fp16 into resident SMEM ----
    {
        const float4* __restrict__ W4 = (const float4*)Wh;
        for (int i = tid; i < 8192; i += 256) {
            int r  = i >> 8;          // n row 0..31
            int f4 = i & 255;         // float4 col
            int c  = f4 >> 4;         // chunk 0..15
            int fc = f4 & 15;
            float4 v = W4[(size_t)(n0 + r) * 256 + f4];
            round_store_h(v, smem + OFF_WH + c * 4096,
                          (uint32_t)(r * 128 + fc * 8));
        }
    }
    __syncthreads();

    // warp mapping: 8 warps = 4m-rowgrps x 2n; warp tile 16(m) x 16(n)
    const int rowgrp = wid >> 1;
    const int wm = rowgrp * 16;
    const int wn = (wid & 1) * 16;
    const int t4 = lane >> 2, cp = (lane & 3) * 2;
    const int q = lane >> 3;
    float2 bv[2];
    bv[0] = *(const float2*)&bh[n0 + wn + 0 + cp];
    bv[1] = *(const float2*)&bh[n0 + wn + 8 + cp];

    // B ldsm base offsets per ksl (0..3), chunk-relative (swizzled)
    uint32_t boff[4];
    {
        uint32_t rn = (uint32_t)(wn + (lane & 7) + (q >> 1) * 8);
        #pragma unroll
        for (int ksl = 0; ksl < 4; ksl++)
            boff[ksl] = sw128(rn * 128 + (uint32_t)(ksl * 32 + (q & 1) * 16));
    }

    const int kstep_w = bx * 2 + (wn >> 4);
    unsigned* flags = &g_done[(by * 4) * 32];
    unsigned* myflag = &flags[(bx >> 3) * 32];

    // flag wait: spin-first (32), then nanosleep backoff
    #define WAITFLAG(S, TGT)                                                 \
        do {                                                                 \
            if (lane == 0) {                                                 \
                unsigned cur; int sp = 0;                                    \
                while (1) {                                                  \
                    asm volatile("ld.acquire.gpu.u32 %0, [%1];"              \
                                 : "=r"(cur) : "l"(&flags[(S) * 32]));       \
                    if (cur >= (TGT)) break;                                 \
                    if (++sp > 32) __nanosleep(32);                          \
                }                                                            \
            }                                                                \
            __syncwarp();                                                    \
        } while (0)

    #define LOADSTAGE(DST, S)                                                \
        do {                                                                 \
            _Pragma("unroll")                                                \
            for (int i = 0; i < 16; i++)                                     \
                DST[i] = ldgcg4(fbase + ((S) * 16 + i) * 32);                \
        } while (0)

    #define COMPSTAGE(SRC, S)                                                \
        do {                                                                 \
            _Pragma("unroll")                                                \
            for (int i = 0; i < 16; i++) {                                   \
                const int ks = (S) * 16 + i;                                 \
                const int ch = ks >> 2, ksl = ks & 3;                        \
                uint32_t bf[4];                                              \
                ldsm4(bf, uWh + ch * 4096 + boff[ksl]);                      \
                if (i & 1) {                                                 \
                    mma_f16(c1[0], (const uint32_t*)&SRC[i], bf[0], bf[1]);  \
                    mma_f16(c1[1], (const uint32_t*)&SRC[i], bf[2], bf[3]);  \
                } else {                                                     \
                    mma_f16(c0[0], (const uint32_t*)&SRC[i], bf[0], bf[1]);  \
                    mma_f16(c0[1], (const uint32_t*)&SRC[i], bf[2], bf[3]);  \
                }                                                            \
            }                                                                \
        } while (0)

    for (int t = 0; t < TSTEPS; t++) {
        float c0[2][4] = {}, c1[2][4] = {};
        float* __restrict__ xp = hall + (size_t)t * BH_;

        // prefetch xp for epilogue
        float2 xv[2][2];
        #pragma unroll
        for (int ni = 0; ni < 2; ni++)
            #pragma unroll
            for (int h = 0; h < 2; h++) {
                const int r = m0 + wm + t4 + h * 8;
                const int col = n0 + wn + ni * 8 + cp;
                xv[ni][h] = *(const float2*)&xp[(size_t)r * H_ + col];
            }

        if (t > 0) {
            const uint4* __restrict__ fbase =
                &g_frag[(t - 1) & 1][by][rowgrp][0][lane];
            const unsigned tgt = 64u * (unsigned)t;

            uint4 a0[16], a1[16];
            WAITFLAG(0, tgt);
            LOADSTAGE(a0, 0);

            WAITFLAG(1, tgt);
            LOADSTAGE(a1, 1);
            COMPSTAGE(a0, 0);

            WAITFLAG(2, tgt);
            LOADSTAGE(a0, 2);
            COMPSTAGE(a1, 1);

            WAITFLAG(3, tgt);
            LOADSTAGE(a1, 3);
            COMPSTAGE(a0, 2);

            COMPSTAGE(a1, 3);

            #pragma unroll
            for (int ni = 0; ni < 2; ni++)
                #pragma unroll
                for (int r = 0; r < 4; r++)
                    c0[ni][r] += c1[ni][r];
        }

        // ---- epilogue: tanh -> frag store -> RELEASE -> fp32 stores ----
        {
            float v[2][2][2];   // [ni][h][pair]
            #pragma unroll
            for (int ni = 0; ni < 2; ni++)
                #pragma unroll
                for (int h = 0; h < 2; h++) {
                    float v0 = tanhf(c0[ni][h * 2]     + xv[ni][h].x + bv[ni].x);
                    float v1 = tanhf(c0[ni][h * 2 + 1] + xv[ni][h].y + bv[ni].y);
                    v[ni][h][0] = v0; v[ni][h][1] = v1;
                }

            // fragment store + release FIRST (consumer critical path)
            uint4 fv;
            fv.x = pack2h(__float2half(v[0][0][0]), __float2half(v[0][0][1]));
            fv.y = pack2h(__float2half(v[0][1][0]), __float2half(v[0][1][1]));
            fv.z = pack2h(__float2half(v[1][0][0]), __float2half(v[1][0][1]));
            fv.w = pack2h(__float2half(v[1][1][0]), __float2half(v[1][1][1]));
            stg4(&g_frag[t & 1][by][rowgrp][kstep_w][lane], fv);
            if (t < TSTEPS - 1) {
                __syncwarp();
                if (lane == 0)
                    asm volatile("red.release.gpu.global.add.u32 [%0], %1;"
                                 :: "l"(myflag), "r"(1u) : "memory");
            }

            // fp32 outputs (off the inter-CTA critical path)
            #pragma unroll
            for (int ni = 0; ni < 2; ni++) {
                const int col = n0 + wn + ni * 8 + cp;
                #pragma unroll
                for (int h = 0; h < 2; h++) {
                    const int r = m0 + wm + t4 + h * 8;
                    *(float2*)&xp[(size_t)r * H_ + col] =
                        make_float2(v[ni][h][0], v[ni][h][1]);
                    if (t == TSTEPS - 1)
                        *(float2*)&hfinal[(size_t)r * H_ + col] =
                            make_float2(v[ni][h][0], v[ni][h][1]);
                }
            }
        }
    }

    // ---- in-kernel flag reset: last-finishing CTA zeroes flags ----
    __syncthreads();
    if (tid == 0) {
        unsigned prev;
        asm volatile("atom.add.release.gpu.u32 %0, [%1], 1;"
                     : "=r"(prev) : "l"(&g_finish));
        if (prev == 127u) {
            #pragma unroll
            for (int i = 0; i < 16; i++)
                asm volatile("st.relaxed.gpu.u32 [%0], %1;"
                             :: "l"(&g_done[i * 32]), "r"(0u));
            asm volatile("st.relaxed.gpu.u32 [%0], %1;"
                         :: "l"(&g_finish), "r"(0u));
        }
    }

    #undef WAITFLAG
    #undef LOADSTAGE
    #undef COMPSTAGE
}

// ---------------------------------------------------------------------------
// kernel_launch: gemm_xp, then persistent scan (flags self-reset).
// ---------------------------------------------------------------------------
extern "C" void kernel_launch(void* const* d_in, const int* in_sizes, int n_in,
                              void* d_out, int out_size)
{
    const float* x  = (const float*)d_in[0];
    const float* Wx = (const float*)d_in[1];
    const float* bx = (const float*)d_in[2];
    const float* Wh = (const float*)d_in[3];
    const float* bh = (const float*)d_in[4];

    float* out    = (float*)d_out;
    float* hfinal = out;                 // [B_ * H_]
    float* hall   = out + BH_;           // [TSTEPS * B_ * H_]

    static int smem_set = 0;
    if (!smem_set) {
        cudaFuncSetAttribute(rnn_scan_kernel,
                             cudaFuncAttributeMaxDynamicSharedMemorySize,
                             SMEM_TOTAL);
        smem_set = 1;
    }

    // Phase 1: xp for all timesteps
    gemm_xp_kernel<<<dim3(16, 1024), 256>>>(x, Wx, bx, hall);

    // Phase 2: persistent tensor-core scan (128 CTAs, all resident)
    rnn_scan_kernel<<<dim3(32, 4), 256, SMEM_TOTAL>>>(Wh, bh, hall, hfinal);
}

// round 14
// speedup vs baseline: 2.4465x; 1.6002x over previous
#include <cuda_runtime.h>
#include <cuda_bf16.h>
#include <cuda_fp16.h>
#include <stdint.h>
#include <math.h>

// Problem constants
#define TSTEPS 512
#define B_ 256
#define H_ 1024
#define K_ 1024
#define BH_ (B_ * H_)

// Scan SMEM: Wh resident fp16, 16 chunks x 4KB (32n x 64k each)
#define OFF_WH   0
#define SMEM_TOTAL 65536

// h in mma-A-fragment layout:
// [parity][mtile(4)][rowgrp(4)][kstep(64)][lane(32)] x uint4  = 2MB total
__device__ uint4 g_frag[2][4][4][64][32];
// per-(mtile, stage) monotonic warp-arrival flags (padded to 128B lines)
__device__ unsigned g_done[4 * 4 * 32];
// scan-finish counter (for in-kernel flag reset)
__device__ unsigned g_finish;

// ---------------------------------------------------------------------------
// Helpers
// ---------------------------------------------------------------------------
__device__ __forceinline__ uint32_t smem_u32(const void* p) {
    uint32_t a;
    asm("{ .reg .u64 t; cvta.to.shared.u64 t, %1; cvt.u32.u64 %0, t; }"
        : "=r"(a) : "l"(p));
    return a;
}
__device__ __forceinline__ uint32_t sw128(uint32_t off) {
    return off ^ ((off >> 3) & 0x70);
}
__device__ __forceinline__ void ldsm4(uint32_t r[4], uint32_t addr) {
    asm volatile("ldmatrix.sync.aligned.m8n8.x4.shared.b16 {%0,%1,%2,%3}, [%4];"
                 : "=r"(r[0]), "=r"(r[1]), "=r"(r[2]), "=r"(r[3]) : "r"(addr));
}
__device__ __forceinline__ void mma_f16(float c[4], const uint32_t a[4],
                                        uint32_t b0, uint32_t b1) {
    asm volatile(
        "mma.sync.aligned.m16n8k16.row.col.f32.f16.f16.f32 "
        "{%0,%1,%2,%3}, {%4,%5,%6,%7}, {%8,%9}, {%0,%1,%2,%3};"
        : "+f"(c[0]), "+f"(c[1]), "+f"(c[2]), "+f"(c[3])
        : "r"(a[0]), "r"(a[1]), "r"(a[2]), "r"(a[3]), "r"(b0), "r"(b1));
}
__device__ __forceinline__ uint32_t pack2h(__half a, __half b) {
    return ((uint32_t)__half_as_ushort(b) << 16) | __half_as_ushort(a);
}
__device__ __forceinline__ void round_store_h(float4 v, char* base, uint32_t off) {
    uint32_t s = sw128(off);
    *(uint2*)(base + s) = make_uint2(
        pack2h(__float2half(v.x), __float2half(v.y)),
        pack2h(__float2half(v.z), __float2half(v.w)));
}
__device__ __forceinline__ uint4 ldgcg4(const uint4* p) {
    uint4 v;
    asm volatile("ld.global.cg.v4.u32 {%0,%1,%2,%3}, [%4];"
                 : "=r"(v.x), "=r"(v.y), "=r"(v.z), "=r"(v.w) : "l"(p));
    return v;
}
__device__ __forceinline__ void stg4(uint4* p, uint4 v) {
    asm volatile("st.global.v4.u32 [%0], {%1,%2,%3,%4};"
                 :: "l"(p), "r"(v.x), "r"(v.y), "r"(v.z), "r"(v.w) : "memory");
}

// ---------------------------------------------------------------------------
// Phase 1: xp[m,n] = x[m,:] . Wx[n,:] + bx[n]
// fp16 1-term HMMA, BM=128 x BN=128, CK=64, 256 threads.
// 8 warps = 4m x 2n; warp tile 32m x 64n. Grid (8, 1024): n-tiles on
// consecutive bids so x tiles hit L2 (x read 8x through L2, once from DRAM).
// ---------------------------------------------------------------------------
__global__ void __launch_bounds__(256, 1) gemm_xp_kernel(
    const float* __restrict__ A, const float* __restrict__ W,
    const float* __restrict__ bias, float* __restrict__ C)
{
    __shared__ __align__(1024) char sA[128 * 128];   // 16KB fp16
    __shared__ __align__(1024) char sB[128 * 128];   // 16KB fp16

    const int tid = threadIdx.x;
    const int wid = tid >> 5, lane = tid & 31;
    const int m0 = blockIdx.y * 128;
    const int n0 = blockIdx.x * 128;
    const int wm = (wid >> 1) * 32;      // 0,32,64,96
    const int wn = (wid & 1) * 64;       // 0,64

    const uint32_t uA = smem_u32(sA), uB = smem_u32(sB);

    const int ar = tid >> 4;             // 0..15
    const int ac = tid & 15;             // float4 col 0..15
    const float4* __restrict__ A4 = (const float4*)A;
    const float4* __restrict__ W4 = (const float4*)W;

    float c[2][8][4] = {};               // [mi][ni][reg]
    float4 pa[8], pb[8];

    #pragma unroll
    for (int p = 0; p < 8; p++) {
        pa[p] = A4[(size_t)(m0 + ar + p * 16) * 256 + ac];
        pb[p] = W4[(size_t)(n0 + ar + p * 16) * 256 + ac];
    }

    for (int ch = 0; ch < 16; ch++) {
        if (ch > 0) __syncthreads();
        #pragma unroll
        for (int p = 0; p < 8; p++) {
            round_store_h(pa[p], sA, (uint32_t)((ar + p * 16) * 128 + ac * 8));
            round_store_h(pb[p], sB, (uint32_t)((ar + p * 16) * 128 + ac * 8));
        }
        __syncthreads();

        if (ch < 15) {
            const int kc = (ch + 1) * 16;
            #pragma unroll
            for (int p = 0; p < 8; p++) {
                pa[p] = A4[(size_t)(m0 + ar + p * 16) * 256 + kc + ac];
                pb[p] = W4[(size_t)(n0 + ar + p * 16) * 256 + kc + ac];
            }
        }

        #pragma unroll
        for (int ks = 0; ks < 4; ks++) {
            const int q = lane >> 3;
            uint32_t ah[2][4];
            #pragma unroll
            for (int mi = 0; mi < 2; mi++) {
                uint32_t r = (uint32_t)(wm + mi * 16 + (lane & 7) + (q & 1) * 8);
                uint32_t kb = (uint32_t)(ks * 32 + (q >> 1) * 16);
                ldsm4(ah[mi], uA + sw128(r * 128 + kb));
            }
            uint32_t bf[4][4];
            #pragma unroll
            for (int g = 0; g < 4; g++) {
                uint32_t rn = (uint32_t)(wn + g * 16 + (lane & 7) + (q >> 1) * 8);
                uint32_t kb = (uint32_t)(ks * 32 + (q & 1) * 16);
                ldsm4(bf[g], uB + sw128(rn * 128 + kb));
            }
            #pragma unroll
            for (int mi = 0; mi < 2; mi++)
                #pragma unroll
                for (int g = 0; g < 4; g++) {
                    mma_f16(c[mi][g * 2],     ah[mi], bf[g][0], bf[g][1]);
                    mma_f16(c[mi][g * 2 + 1], ah[mi], bf[g][2], bf[g][3]);
                }
        }
    }

    const int t4 = lane >> 2, cp = (lane & 3) * 2;
    #pragma unroll
    for (int mi = 0; mi < 2; mi++) {
        #pragma unroll
        for (int ni = 0; ni < 8; ni++) {
            const int col = n0 + wn + ni * 8 + cp;
            float2 bv = *(const float2*)&bias[col];
            const int r0 = m0 + wm + mi * 16 + t4;
            float2 v0 = make_float2(c[mi][ni][0] + bv.x, c[mi][ni][1] + bv.y);
            float2 v1 = make_float2(c[mi][ni][2] + bv.x, c[mi][ni][3] + bv.y);
            *(float2*)&C[(size_t)r0 * H_ + col] = v0;
            *(float2*)&C[(size_t)(r0 + 8) * H_ + col] = v1;
        }
    }
}

// ---------------------------------------------------------------------------
// Phase 2: persistent scan — IDENTICAL to the R13 best-known config.
// Grid (32, 4) = 128 CTAs, 256 threads; 8 warps (4 rowgrps x 2 n), warp tile
// 16m x 16n, depth-2 stage pipeline, atomic-counter stage flags, epilogue
// ordered frag-store + release before fp32 output stores.
// ---------------------------------------------------------------------------
__global__ void __launch_bounds__(256, 1) rnn_scan_kernel(
    const float* __restrict__ Wh, const float* __restrict__ bh,
    float* __restrict__ hall, float* __restrict__ hfinal)
{
    extern __shared__ __align__(1024) char smem[];

    const int tid = threadIdx.x;
    const int wid = tid >> 5, lane = tid & 31;
    const int bx = blockIdx.x;           // n-tile 0..31
    const int by = blockIdx.y;           // m-tile 0..3
    const int n0 = bx * 32;
    const int m0 = by * 64;

    const uint32_t uWh = smem_u32(smem + OFF_WH);

    // ---- one-time: round Wh tile to fp16 into resident SMEM ----
    {
        const float4* __restrict__ W4 = (const float4*)Wh;
        for (int i = tid; i < 8192; i += 256) {
            int r  = i >> 8;          // n row 0..31
            int f4 = i & 255;         // float4 col
            int c  = f4 >> 4;         // chunk 0..15
            int fc = f4 & 15;
            float4 v = W4[(size_t)(n0 + r) * 256 + f4];
            round_store_h(v, smem + OFF_WH + c * 4096,
                          (uint32_t)(r * 128 + fc * 8));
        }
    }
    __syncthreads();

    // warp mapping: 8 warps = 4m-rowgrps x 2n; warp tile 16(m) x 16(n)
    const int rowgrp = wid >> 1;
    const int wm = rowgrp * 16;
    const int wn = (wid & 1) * 16;
    const int t4 = lane >> 2, cp = (lane & 3) * 2;
    const int q = lane >> 3;
    float2 bv[2];
    bv[0] = *(const float2*)&bh[n0 + wn + 0 + cp];
    bv[1] = *(const float2*)&bh[n0 + wn + 8 + cp];

    // B ldsm base offsets per ksl (0..3), chunk-relative (swizzled)
    uint32_t boff[4];
    {
        uint32_t rn = (uint32_t)(wn + (lane & 7) + (q >> 1) * 8);
        #pragma unroll
        for (int ksl = 0; ksl < 4; ksl++)
            boff[ksl] = sw128(rn * 128 + (uint32_t)(ksl * 32 + (q & 1) * 16));
    }

    const int kstep_w = bx * 2 + (wn >> 4);
    unsigned* flags = &g_done[(by * 4) * 32];
    unsigned* myflag = &flags[(bx >> 3) * 32];

    // flag wait: spin-first (32), then nanosleep backoff
    #define WAITFLAG(S, TGT)                                                 \
        do {                                                                 \
            if (lane == 0) {                                                 \
                unsigned cur; int sp = 0;                                    \
                while (1) {                                                  \
                    asm volatile("ld.acquire.gpu.u32 %0, [%1];"              \
                                 : "=r"(cur) : "l"(&flags[(S) * 32]));       \
                    if (cur >= (TGT)) break;                                 \
                    if (++sp > 32) __nanosleep(32);                          \
                }                                                            \
            }                                                                \
            __syncwarp();                                                    \
        } while (0)

    #define LOADSTAGE(DST, S)                                                \
        do {                                                                 \
            _Pragma("unroll")                                                \
            for (int i = 0; i < 16; i++)                                     \
                DST[i] = ldgcg4(fbase + ((S) * 16 + i) * 32);                \
        } while (0)

    #define COMPSTAGE(SRC, S)                                                \
        do {                                                                 \
            _Pragma("unroll")                                                \
            for (int i = 0; i < 16; i++) {                                   \
                const int ks = (S) * 16 + i;                                 \
                const int ch = ks >> 2, ksl = ks & 3;                        \
                uint32_t bf[4];                                              \
                ldsm4(bf, uWh + ch * 4096 + boff[ksl]);                      \
                if (i & 1) {                                                 \
                    mma_f16(c1[0], (const uint32_t*)&SRC[i], bf[0], bf[1]);  \
                    mma_f16(c1[1], (const uint32_t*)&SRC[i], bf[2], bf[3]);  \
                } else {                                                     \
                    mma_f16(c0[0], (const uint32_t*)&SRC[i], bf[0], bf[1]);  \
                    mma_f16(c0[1], (const uint32_t*)&SRC[i], bf[2], bf[3]);  \
                }                                                            \
            }                                                                \
        } while (0)

    for (int t = 0; t < TSTEPS; t++) {
        float c0[2][4] = {}, c1[2][4] = {};
        float* __restrict__ xp = hall + (size_t)t * BH_;

        // prefetch xp for epilogue
        float2 xv[2][2];
        #pragma unroll
        for (int ni = 0; ni < 2; ni++)
            #pragma unroll
            for (int h = 0; h < 2; h++) {
                const int r = m0 + wm + t4 + h * 8;
                const int col = n0 + wn + ni * 8 + cp;
                xv[ni][h] = *(const float2*)&xp[(size_t)r * H_ + col];
            }

        if (t > 0) {
            const uint4* __restrict__ fbase =
                &g_frag[(t - 1) & 1][by][rowgrp][0][lane];
            const unsigned tgt = 64u * (unsigned)t;

            uint4 a0[16], a1[16];
            WAITFLAG(0, tgt);
            LOADSTAGE(a0, 0);

            WAITFLAG(1, tgt);
            LOADSTAGE(a1, 1);
            COMPSTAGE(a0, 0);

            WAITFLAG(2, tgt);
            LOADSTAGE(a0, 2);
            COMPSTAGE(a1, 1);

            WAITFLAG(3, tgt);
            LOADSTAGE(a1, 3);
            COMPSTAGE(a0, 2);

            COMPSTAGE(a1, 3);

            #pragma unroll
            for (int ni = 0; ni < 2; ni++)
                #pragma unroll
                for (int r = 0; r < 4; r++)
                    c0[ni][r] += c1[ni][r];
        }

        // ---- epilogue: tanh -> frag store -> RELEASE -> fp32 stores ----
        {
            float v[2][2][2];   // [ni][h][pair]
            #pragma unroll
            for (int ni = 0; ni < 2; ni++)
                #pragma unroll
                for (int h = 0; h < 2; h++) {
                    float v0 = tanhf(c0[ni][h * 2]     + xv[ni][h].x + bv[ni].x);
                    float v1 = tanhf(c0[ni][h * 2 + 1] + xv[ni][h].y + bv[ni].y);
                    v[ni][h][0] = v0; v[ni][h][1] = v1;
                }

            // fragment store + release FIRST (consumer critical path)
            uint4 fv;
            fv.x = pack2h(__float2half(v[0][0][0]), __float2half(v[0][0][1]));
            fv.y = pack2h(__float2half(v[0][1][0]), __float2half(v[0][1][1]));
            fv.z = pack2h(__float2half(v[1][0][0]), __float2half(v[1][0][1]));
            fv.w = pack2h(__float2half(v[1][1][0]), __float2half(v[1][1][1]));
            stg4(&g_frag[t & 1][by][rowgrp][kstep_w][lane], fv);
            if (t < TSTEPS - 1) {
                __syncwarp();
                if (lane == 0)
                    asm volatile("red.release.gpu.global.add.u32 [%0], %1;"
                                 :: "l"(myflag), "r"(1u) : "memory");
            }

            // fp32 outputs (off the inter-CTA critical path)
            #pragma unroll
            for (int ni = 0; ni < 2; ni++) {
                const int col = n0 + wn + ni * 8 + cp;
                #pragma unroll
                for (int h = 0; h < 2; h++) {
                    const int r = m0 + wm + t4 + h * 8;
                    *(float2*)&xp[(size_t)r * H_ + col] =
                        make_float2(v[ni][h][0], v[ni][h][1]);
                    if (t == TSTEPS - 1)
                        *(float2*)&hfinal[(size_t)r * H_ + col] =
                            make_float2(v[ni][h][0], v[ni][h][1]);
                }
            }
        }
    }

    // ---- in-kernel flag reset: last-finishing CTA zeroes flags ----
    __syncthreads();
    if (tid == 0) {
        unsigned prev;
        asm volatile("atom.add.release.gpu.u32 %0, [%1], 1;"
                     : "=r"(prev) : "l"(&g_finish));
        if (prev == 127u) {
            #pragma unroll
            for (int i = 0; i < 16; i++)
                asm volatile("st.relaxed.gpu.u32 [%0], %1;"
                             :: "l"(&g_done[i * 32]), "r"(0u));
            asm volatile("st.relaxed.gpu.u32 [%0], %1;"
                         :: "l"(&g_finish), "r"(0u));
        }
    }

    #undef WAITFLAG
    #undef LOADSTAGE
    #undef COMPSTAGE
}

// ---------------------------------------------------------------------------
// kernel_launch: gemm_xp (fp16 1-term), then persistent scan (self-reset).
// ---------------------------------------------------------------------------
extern "C" void kernel_launch(void* const* d_in, const int* in_sizes, int n_in,
                              void* d_out, int out_size)
{
    const float* x  = (const float*)d_in[0];
    const float* Wx = (const float*)d_in[1];
    const float* bx = (const float*)d_in[2];
    const float* Wh = (const float*)d_in[3];
    const float* bh = (const float*)d_in[4];

    float* out    = (float*)d_out;
    float* hfinal = out;                 // [B_ * H_]
    float* hall   = out + BH_;           // [TSTEPS * B_ * H_]

    static int smem_set = 0;
    if (!smem_set) {
        cudaFuncSetAttribute(rnn_scan_kernel,
                             cudaFuncAttributeMaxDynamicSharedMemorySize,
                             SMEM_TOTAL);
        smem_set = 1;
    }

    // Phase 1: xp for all timesteps (fp16 1-term, BN=128)
    gemm_xp_kernel<<<dim3(8, 1024), 256>>>(x, Wx, bx, hall);

    // Phase 2: persistent tensor-core scan (128 CTAs, all resident)
    rnn_scan_kernel<<<dim3(32, 4), 256, SMEM_TOTAL>>>(Wh, bh, hall, hfinal);
}